// round 16
// baseline (speedup 1.0000x reference)
#include <cuda_runtime.h>
#include <cuda_fp16.h>
#include <math.h>
#include <stdint.h>

// ---------------------------------------------------------------------------
// MultidomainEncoder: B=4, N=M=1024, H=512.
// Round 13: TN-templated GEMM (128/64) to fix wave-starved AV/Wf launches;
// warp-reduce tproj prep kernels. Rank-4 skinny projections, prob-fold AV,
// fused [x|R] Wf unchanged.
// ---------------------------------------------------------------------------

#define RR   4096          // B*N == B*M rows
#define HD   512           // model dim
#define QW   1536          // fused QKV row width

__device__ float  g_e   [RR * HD];                    // exact encoder state
__device__ __half g_enc [3 * (size_t)RR * 1024];      // region0: [x|R]; region2: decoder [q|R]
__device__ float  g_qb  [RR * HD];                    // exact decoder state
__device__ float  g_T   [RR * HD];
__device__ __half g_QKV [2 * (size_t)RR * QW];        // QKV buffers (state / x2)
__device__ __half g_Vt  [(size_t)8 * 1024 * 1024];    // transposed V
__device__ float  g_S   [(size_t)32 * 1024 * 1024];   // pre-softmax scores (fp32)
__device__ __half g_S16 [(size_t)8 * 1024 * 2048];    // folded probs (fp16)
__device__ __half g_Wc  [4 * (size_t)QW * 512];       // transposed fused QKV weights
__device__ __half g_Wf  [4 * (size_t)512 * 1024];     // transposed full Wf per layer
__device__ float  g_F   [4 * (size_t)RR * 4];         // encoder rank-4 factors per stream
__device__ float  g_Fdk [RR * 4];                     // decoder K factor [cx,1,0,0]
__device__ float  g_Fdq [RR * 4];                     // decoder Q factor [tx,1,0,0]
__device__ float  g_Tenc[2 * 4 * QW];                 // M_aug @ Wqkv_i  (fp32)
__device__ float  g_Tdk [2 * 4 * 512];                // Mcx @ Wk_ca_i
__device__ float  g_Tq0 [4 * 512];                    // Mtx @ Wq_ca_0

static const long QBUF  = (long)RR * QW;              // QKV buffer stride (halfs)
static const long SSEGf = (long)8 * 1024 * 1024;      // S segment per combo (floats)
static const long ENCR  = (long)RR * 1024;            // one g_enc region (halfs)

// ---------------------------------------------------------------------------
// helpers
// ---------------------------------------------------------------------------
__device__ __forceinline__ void mma_f16(float c[4], const uint32_t a[4], const uint32_t b[2]) {
    asm volatile(
        "mma.sync.aligned.m16n8k16.row.col.f32.f16.f16.f32 "
        "{%0,%1,%2,%3}, {%4,%5,%6,%7}, {%8,%9}, {%0,%1,%2,%3};"
        : "+f"(c[0]), "+f"(c[1]), "+f"(c[2]), "+f"(c[3])
        : "r"(a[0]), "r"(a[1]), "r"(a[2]), "r"(a[3]), "r"(b[0]), "r"(b[1]));
}

__device__ __forceinline__ void cp16(uint32_t* dst, const void* src) {
    uint32_t d = (uint32_t)__cvta_generic_to_shared(dst);
    asm volatile("cp.async.cg.shared.global [%0], [%1], 16;" :: "r"(d), "l"(src));
}
#define CP_COMMIT() asm volatile("cp.async.commit_group;" ::: "memory")
#define CP_WAIT1()  asm volatile("cp.async.wait_group 1;"  ::: "memory")
#define CP_WAIT0()  asm volatile("cp.async.wait_group 0;"  ::: "memory")

struct Offs { long a[4]; long b[4]; long c[4]; };

// ---------------------------------------------------------------------------
// fp16 GEMM:  C[m,n] = alpha * sum_k A[m,k] * B[n,k]  [+bias] [+C]
// A: [M,K] row-major fp16 (lda); B: [N,K] row-major fp16 (ldb).
// C: fp32 (outHalf=0) or fp16 (outHalf=1).
// Tile 128 x TN x 32, 256 threads (8 warps = 2M x 4N).
//   TN=128: warp tile 64x32 (4 n-frags);  TN=64: warp tile 64x16 (2 n-frags).
// ---------------------------------------------------------------------------
#define WPR 20   // words per smem row (16 data + 4 pad)

template<int TN>
__global__ void __launch_bounds__(256)
gemm_h(const __half* __restrict__ A, const __half* __restrict__ B,
       void* __restrict__ Cv, const float* __restrict__ bias,
       int K, int lda, int ldb, int ldc,
       long sAb, long sAh, long sBb, long sBh, long sCb, long sCh,
       int nh, int nzc, Offs off, float alpha, int accumulate, int outHalf)
{
    constexpr int NT = TN / 32;          // n-frags per warp

    __shared__ uint32_t sA[2][128 * WPR];
    __shared__ uint32_t sB[2][TN * WPR];

    int z   = blockIdx.z;
    int cmb = z / nzc;
    int inn = z - cmb * nzc;
    int bb  = inn / nh;
    int hh  = inn - bb * nh;
    A += off.a[cmb] + (long)bb * sAb + (long)hh * sAh;
    B += off.b[cmb] + (long)bb * sBb + (long)hh * sBh;
    long coff = off.c[cmb] + (long)bb * sCb + (long)hh * sCh;

    const int row0 = blockIdx.y * 128;
    const int col0 = blockIdx.x * TN;
    const int tid  = threadIdx.x;
    const int wid  = tid >> 5;
    const int lane = tid & 31;
    const int wM0 = (wid & 1) * 64;
    const int wN0 = (wid >> 1) * (TN / 4);
    const int gid = lane >> 2;
    const int tig = lane & 3;

    float acc[4][NT][4] = {};

    const int lrow = tid >> 1;
    const int lsel = tid & 1;
    const int brow = tid >> 2;
    const int bsel = tid & 3;

    auto loadTile = [&](int t, int s) {
        const __half* ga = A + (long)(row0 + lrow) * lda + t * 32 + lsel * 16;
        uint32_t* sa = &sA[s][lrow * WPR + lsel * 8];
        cp16(sa, ga); cp16(sa + 4, ga + 8);
        if (TN == 128) {
            const __half* gb = B + (long)(col0 + lrow) * ldb + t * 32 + lsel * 16;
            uint32_t* sb = &sB[s][lrow * WPR + lsel * 8];
            cp16(sb, gb); cp16(sb + 4, gb + 8);
        } else {
            const __half* gb = B + (long)(col0 + brow) * ldb + t * 32 + bsel * 8;
            uint32_t* sb = &sB[s][brow * WPR + bsel * 4];
            cp16(sb, gb);
        }
    };

    const int nT = K / 32;
    loadTile(0, 0);
    CP_COMMIT();

    for (int t = 0; t < nT; t++) {
        int s = t & 1;
        if (t + 1 < nT) {
            loadTile(t + 1, s ^ 1);
            CP_COMMIT();
            CP_WAIT1();
        } else {
            CP_WAIT0();
        }
        __syncthreads();

        const uint32_t* Ap = sA[s];
        const uint32_t* Bp = sB[s];
#pragma unroll
        for (int ko = 0; ko < 16; ko += 8) {
            uint32_t af[4][4], bfr[NT][2];
#pragma unroll
            for (int mt = 0; mt < 4; mt++) {
                int m = wM0 + mt * 16 + gid;
                af[mt][0] = Ap[m * WPR + ko + tig];
                af[mt][1] = Ap[(m + 8) * WPR + ko + tig];
                af[mt][2] = Ap[m * WPR + ko + 4 + tig];
                af[mt][3] = Ap[(m + 8) * WPR + ko + 4 + tig];
            }
#pragma unroll
            for (int nt = 0; nt < NT; nt++) {
                int n = wN0 + nt * 8 + gid;
                bfr[nt][0] = Bp[n * WPR + ko + tig];
                bfr[nt][1] = Bp[n * WPR + ko + 4 + tig];
            }
#pragma unroll
            for (int mt = 0; mt < 4; mt++)
#pragma unroll
                for (int nt = 0; nt < NT; nt++)
                    mma_f16(acc[mt][nt], af[mt], bfr[nt]);
        }
        __syncthreads();
    }

    if (!outHalf) {
        float* C = (float*)Cv + coff;
#pragma unroll
        for (int mt = 0; mt < 4; mt++) {
            int r = row0 + wM0 + mt * 16 + gid;
#pragma unroll
            for (int nt = 0; nt < NT; nt++) {
                int c = col0 + wN0 + nt * 8 + tig * 2;
                float b0 = 0.f, b1 = 0.f;
                if (bias) { b0 = bias[c]; b1 = bias[c + 1]; }
                float2 v0, v1;
                v0.x = alpha * acc[mt][nt][0] + b0;
                v0.y = alpha * acc[mt][nt][1] + b1;
                v1.x = alpha * acc[mt][nt][2] + b0;
                v1.y = alpha * acc[mt][nt][3] + b1;
                float* p0 = &C[(long)r * ldc + c];
                float* p1 = &C[(long)(r + 8) * ldc + c];
                if (accumulate) {
                    float2 o0 = *(const float2*)p0, o1 = *(const float2*)p1;
                    v0.x += o0.x; v0.y += o0.y; v1.x += o1.x; v1.y += o1.y;
                }
                *(float2*)p0 = v0;
                *(float2*)p1 = v1;
            }
        }
    } else {
        __half* C = (__half*)Cv + coff;
#pragma unroll
        for (int mt = 0; mt < 4; mt++) {
            int r = row0 + wM0 + mt * 16 + gid;
#pragma unroll
            for (int nt = 0; nt < NT; nt++) {
                int c = col0 + wN0 + nt * 8 + tig * 2;
                __half2 h0 = __floats2half2_rn(alpha * acc[mt][nt][0], alpha * acc[mt][nt][1]);
                __half2 h1 = __floats2half2_rn(alpha * acc[mt][nt][2], alpha * acc[mt][nt][3]);
                *(__half2*)&C[(long)r * ldc + c]       = h0;
                *(__half2*)&C[(long)(r + 8) * ldc + c] = h1;
            }
        }
    }
}

// ---------------------------------------------------------------------------
// Single softmax (L=1024): S fp32 in, S16 fp16 out.
// ---------------------------------------------------------------------------
__global__ void softmax1(const float* __restrict__ S, __half* __restrict__ S16)
{
    const float4* p = (const float4*)(S + (long)blockIdx.x * 1024);
    __half2* o = (__half2*)(S16 + (long)blockIdx.x * 1024);
    int tid = threadIdx.x, lane = tid & 31, wid = tid >> 5;
    __shared__ float red[16];

    float4 v = p[tid];
    float m = fmaxf(fmaxf(v.x, v.y), fmaxf(v.z, v.w));
#pragma unroll
    for (int t = 16; t > 0; t >>= 1) m = fmaxf(m, __shfl_xor_sync(0xffffffffu, m, t));
    if (lane == 0) red[wid] = m;
    __syncthreads();
    m = red[0];
#pragma unroll
    for (int i = 1; i < 8; i++) m = fmaxf(m, red[i]);

    v.x = __expf(v.x - m); v.y = __expf(v.y - m);
    v.z = __expf(v.z - m); v.w = __expf(v.w - m);
    float sum = v.x + v.y + v.z + v.w;
#pragma unroll
    for (int t = 16; t > 0; t >>= 1) sum += __shfl_xor_sync(0xffffffffu, sum, t);
    if (lane == 0) red[8 + wid] = sum;
    __syncthreads();
    sum = red[8];
#pragma unroll
    for (int i = 1; i < 8; i++) sum += red[8 + i];
    float inv = 1.f / sum;

    o[2 * tid]     = __floats2half2_rn(v.x * inv, v.y * inv);
    o[2 * tid + 1] = __floats2half2_rn(v.z * inv, v.w * inv);
}

// ---------------------------------------------------------------------------
// Paired softmax + fold (cross layers): g=0 -> segs {0,2}, g=1 -> segs {1,3}.
// ---------------------------------------------------------------------------
__global__ void softmax_pair(const float* __restrict__ S, __half* __restrict__ S16)
{
    int bid = blockIdx.x;
    int g   = bid >> 13;
    int rem = bid & 8191;
    long roff = (long)rem << 10;
    const float4* pa = (const float4*)(S + (long)g * SSEGf + roff);
    const float4* pb = (const float4*)(S + (long)(g + 2) * SSEGf + roff);
    __half2* out = (__half2*)(S16 + ((long)rem << 11) + ((long)g << 10));
    int tid = threadIdx.x, lane = tid & 31, wid = tid >> 5;
    __shared__ float red[32];

    float4 va = pa[tid], vb = pb[tid];
    float ma = fmaxf(fmaxf(va.x, va.y), fmaxf(va.z, va.w));
    float mb = fmaxf(fmaxf(vb.x, vb.y), fmaxf(vb.z, vb.w));
#pragma unroll
    for (int t = 16; t > 0; t >>= 1) {
        ma = fmaxf(ma, __shfl_xor_sync(0xffffffffu, ma, t));
        mb = fmaxf(mb, __shfl_xor_sync(0xffffffffu, mb, t));
    }
    if (lane == 0) { red[wid] = ma; red[8 + wid] = mb; }
    __syncthreads();
    ma = red[0]; mb = red[8];
#pragma unroll
    for (int i = 1; i < 8; i++) { ma = fmaxf(ma, red[i]); mb = fmaxf(mb, red[8 + i]); }

    va.x = __expf(va.x - ma); va.y = __expf(va.y - ma);
    va.z = __expf(va.z - ma); va.w = __expf(va.w - ma);
    vb.x = __expf(vb.x - mb); vb.y = __expf(vb.y - mb);
    vb.z = __expf(vb.z - mb); vb.w = __expf(vb.w - mb);
    float sa = va.x + va.y + va.z + va.w;
    float sb = vb.x + vb.y + vb.z + vb.w;
#pragma unroll
    for (int t = 16; t > 0; t >>= 1) {
        sa += __shfl_xor_sync(0xffffffffu, sa, t);
        sb += __shfl_xor_sync(0xffffffffu, sb, t);
    }
    if (lane == 0) { red[16 + wid] = sa; red[24 + wid] = sb; }
    __syncthreads();
    sa = red[16]; sb = red[24];
#pragma unroll
    for (int i = 1; i < 8; i++) { sa += red[16 + i]; sb += red[24 + i]; }
    float ia = 1.f / sa, ib = 1.f / sb;

    out[2 * tid]     = __floats2half2_rn(va.x * ia + vb.x * ib, va.y * ia + vb.y * ib);
    out[2 * tid + 1] = __floats2half2_rn(va.z * ia + vb.z * ib, va.w * ia + vb.w * ib);
}

// ---------------------------------------------------------------------------
// transpose V head-slices: src [4*1024 rows, ldsrc] cols [512 + h*d, +d)
//  -> dst[z][d][dstLd] at column offset dstOff  (z = b*hn + h)
// ---------------------------------------------------------------------------
__global__ void transpose_v(const __half* __restrict__ src, __half* __restrict__ dst,
                            int ldsrc, int d, int hn, int dstLd, int dstOff)
{
    __shared__ __half t[32][34];
    int z = blockIdx.z;
    int b = z / hn, h = z - b * hn;
    int m0 = blockIdx.x * 32, c0 = blockIdx.y * 32;
    const __half* s = src + (long)(b * 1024) * ldsrc + 512 + h * d;
    int tx = threadIdx.x, ty = threadIdx.y;
#pragma unroll
    for (int i = 0; i < 4; i++)
        t[ty + i * 8][tx] = s[(long)(m0 + ty + i * 8) * ldsrc + c0 + tx];
    __syncthreads();
    __half* o = dst + (long)z * d * dstLd + dstOff;
#pragma unroll
    for (int i = 0; i < 4; i++)
        o[(long)(c0 + ty + i * 8) * dstLd + m0 + tx] = t[tx][ty + i * 8];
}

// ---------------------------------------------------------------------------
// out = LayerNorm(tmp + res) * g + b ; fp32 exact + fp16 state (ld 1024)
// ---------------------------------------------------------------------------
__global__ void add_ln_kernel(const float* __restrict__ tmp, const float* __restrict__ res,
                              const float* __restrict__ g, const float* __restrict__ b,
                              float* __restrict__ out, __half* __restrict__ outh)
{
    long row = blockIdx.x;
    const float* t = tmp + row * (long)HD;
    const float* r = res + row * (long)HD;
    float* o = out + row * (long)HD;
    __half* oh = outh + row * 1024;
    __shared__ float red[256];
    int tid = threadIdx.x;

    float v0 = t[tid]       + r[tid];
    float v1 = t[tid + 256] + r[tid + 256];
    red[tid] = v0 + v1; __syncthreads();
    for (int s = 128; s > 0; s >>= 1) { if (tid < s) red[tid] += red[tid + s]; __syncthreads(); }
    float mean = red[0] * (1.f / HD);
    __syncthreads();
    float d0 = v0 - mean, d1 = v1 - mean;
    red[tid] = d0 * d0 + d1 * d1; __syncthreads();
    for (int s = 128; s > 0; s >>= 1) { if (tid < s) red[tid] += red[tid + s]; __syncthreads(); }
    float rstd = rsqrtf(red[0] * (1.f / HD) + 1e-5f);
    float w0 = d0 * rstd * g[tid]       + b[tid];
    float w1 = d1 * rstd * g[tid + 256] + b[tid + 256];
    o[tid]       = w0;
    o[tid + 256] = w1;
    oh[tid]       = __float2half_rn(w0);
    oh[tid + 256] = __float2half_rn(w1);
}

// ---------------------------------------------------------------------------
// Input projections
// ---------------------------------------------------------------------------
__global__ void proj_in_kernel(const float* __restrict__ cx, const float* __restrict__ cy,
                               const float* __restrict__ W, const float* __restrict__ bias,
                               float* __restrict__ out, __half* __restrict__ outh,
                               int ldo, int j)
{
    int idx = blockIdx.x * blockDim.x + threadIdx.x;
    if (idx >= RR * HD) return;
    int r = idx >> 9;
    int h = idx & (HD - 1);
    float x0 = cx[r];
    float y0 = cy[r * 8 + j * 2];
    float y1 = cy[r * 8 + j * 2 + 1];
    float v = x0 * W[h] + y0 * W[HD + h] + y1 * W[2 * HD + h] + bias[h];
    if (out) out[idx] = v;
    outh[(long)r * ldo + h] = __float2half_rn(v);
}

__global__ void proj1_kernel(const float* __restrict__ x, const float* __restrict__ W,
                             const float* __restrict__ bias,
                             float* __restrict__ out, __half* __restrict__ outh, int ldo)
{
    int idx = blockIdx.x * blockDim.x + threadIdx.x;
    if (idx >= RR * HD) return;
    int r = idx >> 9;
    int h = idx & (HD - 1);
    float v = x[r] * W[h] + bias[h];
    if (out) out[idx] = v;
    outh[(long)r * ldo + h] = __float2half_rn(v);
}

// ---------------------------------------------------------------------------
// Rank-4 machinery
// ---------------------------------------------------------------------------
__global__ void build_F(const float* __restrict__ cx, const float* __restrict__ cy,
                        const float* __restrict__ tx,
                        float* __restrict__ F, float* __restrict__ Fdk,
                        float* __restrict__ Fdq)
{
    int r = blockIdx.x * blockDim.x + threadIdx.x;
    if (r >= RR) return;
    float c = cx[r];
#pragma unroll
    for (int s = 0; s < 4; s++) {
        float4 v = make_float4(c, cy[r * 8 + s * 2], cy[r * 8 + s * 2 + 1], 1.f);
        *(float4*)&F[((long)s * RR + r) * 4] = v;
    }
    *(float4*)&Fdk[r * 4] = make_float4(c, 1.f, 0.f, 0.f);
    *(float4*)&Fdq[r * 4] = make_float4(tx[r], 1.f, 0.f, 0.f);
}

// Tenc[i][k4][c] = sum_k M_aug[k4][k] * W_{i,sel(c)}[k][c%512]  (warp-per-output)
__global__ void tproj_enc(const float* __restrict__ Wk, const float* __restrict__ Wv,
                          const float* __restrict__ Wq, const float* __restrict__ inW,
                          const float* __restrict__ inb, float* __restrict__ T)
{
    int w = (blockIdx.x * blockDim.x + threadIdx.x) >> 5;
    int lane = threadIdx.x & 31;
    if (w >= 2 * 4 * QW) return;
    int i   = w / (4 * QW);
    int rem = w - i * 4 * QW;
    int k4  = rem / QW;
    int c   = rem - k4 * QW;
    const float* W = (c < 512 ? Wk : c < 1024 ? Wv : Wq) + (long)i * 512 * 512;
    int n = c & 511;
    const float* m = (k4 < 3) ? (inW + k4 * 512) : inb;
    float s = 0.f;
    for (int k = lane; k < 512; k += 32) s += m[k] * W[(long)k * 512 + n];
#pragma unroll
    for (int o = 16; o > 0; o >>= 1) s += __shfl_xor_sync(0xffffffffu, s, o);
    if (lane == 0) T[w] = s;
}

// Tdk[i][k4][n] (k4<2 real, else 0); Tq0[k4][n] from layer-0 Wq. (warp-per-output)
__global__ void tproj_dec(const float* __restrict__ caWk, const float* __restrict__ caWq,
                          const float* __restrict__ cxW, const float* __restrict__ cxb,
                          const float* __restrict__ txW, const float* __restrict__ txb,
                          float* __restrict__ Tdk, float* __restrict__ Tq0)
{
    int w = (blockIdx.x * blockDim.x + threadIdx.x) >> 5;
    int lane = threadIdx.x & 31;
    if (w >= 3 * 4 * 512) return;
    int grp = w / (4 * 512);
    int rem = w - grp * 4 * 512;
    int k4 = rem >> 9, n = rem & 511;
    float s = 0.f;
    if (grp < 2) {
        const float* W = caWk + (long)grp * 512 * 512;
        const float* m = (k4 == 0) ? cxW : (k4 == 1) ? cxb : nullptr;
        if (m) for (int k = lane; k < 512; k += 32) s += m[k] * W[(long)k * 512 + n];
#pragma unroll
        for (int o = 16; o > 0; o >>= 1) s += __shfl_xor_sync(0xffffffffu, s, o);
        if (lane == 0) Tdk[grp * 2048 + rem] = s;
    } else {
        const float* m = (k4 == 0) ? txW : (k4 == 1) ? txb : nullptr;
        if (m) for (int k = lane; k < 512; k += 32) s += m[k] * caWq[(long)k * 512 + n];
#pragma unroll
        for (int o = 16; o > 0; o >>= 1) s += __shfl_xor_sync(0xffffffffu, s, o);
        if (lane == 0) Tq0[rem] = s;
    }
}

// out[r][c] (ld QW) = fp16( F[r][:] . T[:][c] ), c in [0,1536)
__global__ void skinny_full(const float* __restrict__ F, const float* __restrict__ T,
                            __half* __restrict__ out)
{
    int idx = blockIdx.x * blockDim.x + threadIdx.x;
    if (idx >= RR * QW) return;
    int r = idx / QW, c = idx - r * QW;
    float4 f = *(const float4*)&F[(long)r * 4];
    float v = f.x * T[c] + f.y * T[QW + c] + f.z * T[2 * QW + c] + f.w * T[3 * QW + c];
    out[(long)r * QW + c] = __float2half_rn(v);
}

// out[r][outOff + c] (ld QW) over c in [0,512); T rows have leading dim tld.
__global__ void skinny_cols(const float* __restrict__ F, const float* __restrict__ T,
                            int tld, __half* __restrict__ out, int outOff)
{
    int idx = blockIdx.x * blockDim.x + threadIdx.x;
    if (idx >= RR * 512) return;
    int r = idx >> 9, c = idx & 511;
    float4 f = *(const float4*)&F[(long)r * 4];
    float v = f.x * T[c] + f.y * T[tld + c] + f.z * T[2 * tld + c] + f.w * T[3 * tld + c];
    out[(long)r * QW + outOff + c] = __float2half_rn(v);
}

// Direct transposed V for x2 streams (encoder, d=256, hn=2):
// Vt[z][dd][ld=2048] at off 1024; T = Tenc_i + 512 (V block, ld QW).
__global__ void skinny_vt(const float* __restrict__ F, const float* __restrict__ T,
                          __half* __restrict__ Vt)
{
    int idx = blockIdx.x * blockDim.x + threadIdx.x;
    if (idx >= 8 * 256 * 1024) return;
    int n = idx & 1023;
    int rest = idx >> 10;
    int dd = rest & 255;
    int z = rest >> 8;
    int b = z >> 1, h = z & 1;
    long r = (long)b * 1024 + n;
    int c = h * 256 + dd;
    float4 f = *(const float4*)&F[r * 4];
    float v = f.x * T[c] + f.y * T[QW + c] + f.z * T[2 * QW + c] + f.w * T[3 * QW + c];
    Vt[(long)z * 256 * 2048 + (long)dd * 2048 + 1024 + n] = __float2half_rn(v);
}

// ---------------------------------------------------------------------------
// Weight prep (tiled transposes)
// ---------------------------------------------------------------------------
__global__ void wprep_qkv(const float* __restrict__ sWk, const float* __restrict__ sWv,
                          const float* __restrict__ sWq, const float* __restrict__ cWk,
                          const float* __restrict__ cWv, const float* __restrict__ cWq,
                          __half* __restrict__ Wc)
{
    __shared__ float t[32][33];
    int z = blockIdx.z;
    int L = z / 3, m = z - L * 3;
    const float* base;
    if (L < 2) base = (m == 0 ? sWk : m == 1 ? sWv : sWq) + (long)L * 512 * 512;
    else       base = (m == 0 ? cWk : m == 1 ? cWv : cWq) + (long)(L - 2) * 512 * 512;
    __half* dst = Wc + (long)L * QW * 512 + (long)m * 512 * 512;
    int n0 = blockIdx.x * 32, k0 = blockIdx.y * 32;
    int tx = threadIdx.x, ty = threadIdx.y;
#pragma unroll
    for (int i = 0; i < 4; i++)
        t[ty + i * 8][tx] = base[(long)(k0 + ty + i * 8) * 512 + n0 + tx];
    __syncthreads();
#pragma unroll
    for (int i = 0; i < 4; i++)
        dst[(long)(n0 + ty + i * 8) * 512 + k0 + tx] = __float2half_rn(t[tx][ty + i * 8]);
}

__global__ void wprep_wf(const float* __restrict__ sWf, const float* __restrict__ cWf,
                         __half* __restrict__ Wf)
{
    __shared__ float t[32][33];
    int z = blockIdx.z;
    const float* src = (z < 2 ? sWf : cWf) + (long)(z & 1) * 1024 * 512;
    __half* dst = Wf + (long)z * 512 * 1024;
    int k0 = blockIdx.x * 32, n0 = blockIdx.y * 32;
    int tx = threadIdx.x, ty = threadIdx.y;
#pragma unroll
    for (int i = 0; i < 4; i++)
        t[ty + i * 8][tx] = src[(long)(k0 + ty + i * 8) * 512 + n0 + tx];
    __syncthreads();
#pragma unroll
    for (int i = 0; i < 4; i++)
        dst[(long)(n0 + ty + i * 8) * 1024 + k0 + tx] = __float2half_rn(t[tx][ty + i * 8]);
}

// ---------------------------------------------------------------------------
// Host orchestration
// ---------------------------------------------------------------------------
static void gemmH(int tn, const __half* A, const __half* B, void* C, const float* bias,
                  int M, int N, int K, int lda, int ldb, int ldc,
                  long sAb, long sAh, long sBb, long sBh, long sCb, long sCh,
                  int nb, int nh, int ncomb, const Offs& off,
                  float alpha, int acc, int outHalf)
{
    dim3 grid(N / tn, M / 128, ncomb * nb * nh);
    if (tn == 128)
        gemm_h<128><<<grid, 256>>>(A, B, C, bias, K, lda, ldb, ldc,
                                   sAb, sAh, sBb, sBh, sCb, sCh,
                                   nh, nb * nh, off, alpha, acc, outHalf);
    else
        gemm_h<64><<<grid, 256>>>(A, B, C, bias, K, lda, ldb, ldc,
                                  sAb, sAh, sBb, sBh, sCb, sCh,
                                  nh, nb * nh, off, alpha, acc, outHalf);
}

struct Bufs {
    float *e, *qb, *T, *S, *F, *Fdk, *Fdq, *Tenc, *Tdk, *Tq0;
    __half *enc, *QKV, *Vt, *S16, *Wc, *Wf;
};

// Encoder layer. mode: 0 = self via skinny QKV (layer 1 only),
//                      1 = self via full GEMM, 2 = cross-domain.
static void sc_attn(Bufs& Z, int mode, const float* Fs, const float* Tl,
                    const __half* Wct, const __half* WfT,
                    const float* bf, const float* gg, const float* bb)
{
    const float scale = rsqrtf(256.f);
    Offs z0 = {};
    bool same = (mode != 2);
    const int nbF = (RR * QW + 255) / 256;
    const int nbC = (RR * 512 + 255) / 256;
    const int nbV = (8 * 256 * 1024 + 255) / 256;

    // state QKV
    if (mode == 0)
        skinny_full<<<nbF, 256>>>(Fs, Tl, Z.QKV);
    else
        gemmH(128, Z.enc, Wct, Z.QKV, nullptr, RR, QW, HD, 1024, HD, QW,
              0,0,0,0,0,0, 1,1,1, z0, 1.f, 0, 1);

    if (mode == 2) {
        skinny_cols<<<nbC, 256>>>(Fs, Tl,        QW, Z.QKV + QBUF, 0);
        skinny_cols<<<nbC, 256>>>(Fs, Tl + 1024, QW, Z.QKV + QBUF, 1024);
        skinny_vt<<<nbV, 256>>>(Fs, Tl + 512, Z.Vt);
        transpose_v<<<dim3(32, 8, 8), dim3(32, 8)>>>(Z.QKV, Z.Vt, QW, 256, 2, 2048, 0);
    } else {
        transpose_v<<<dim3(32, 8, 8), dim3(32, 8)>>>(Z.QKV, Z.Vt, QW, 256, 2, 1024, 0);
    }

    // QK scores -> S (fp32)
    {
        Offs oQK = {};
        int nc = 1;
        if (same) {
            oQK.a[0] = 1024;
        } else {
            const long selQ[4] = {0, 1, 1, 0};
            const long selK[4] = {0, 1, 0, 1};
            for (int c = 0; c < 4; c++) {
                oQK.a[c] = selQ[c] * QBUF + 1024;
                oQK.b[c] = selK[c] * QBUF;
                oQK.c[c] = c * SSEGf;
            }
            nc = 4;
        }
        gemmH(128, Z.QKV, Z.QKV, Z.S, nullptr, 1024, 1024, 256, QW, QW, 1024,
              (long)1024 * QW, 256, (long)1024 * QW, 256,
              (long)2 * 1024 * 1024, (long)1024 * 1024,
              4, 2, nc, oQK, scale, 0, 0);
    }

    if (same) {
        softmax1<<<8 * 1024, 256>>>(Z.S, Z.S16);
        gemmH(64, Z.S16, Z.Vt, Z.enc + 512, nullptr, 1024, 256, 1024, 1024, 1024, 1024,
              (long)2 * 1024 * 1024, (long)1024 * 1024,
              (long)2 * 256 * 1024, (long)256 * 1024,
              (long)1024 * 1024, 256,
              4, 2, 1, z0, 4.f, 0, 1);
    } else {
        softmax_pair<<<2 * 8 * 1024, 256>>>(Z.S, Z.S16);
        gemmH(64, Z.S16, Z.Vt, Z.enc + 512, nullptr, 1024, 256, 2048, 2048, 2048, 1024,
              (long)2 * 1024 * 2048, (long)1024 * 2048,
              (long)2 * 256 * 2048, (long)256 * 2048,
              (long)1024 * 1024, 256,
              4, 2, 1, z0, 1.f, 0, 1);
    }

    gemmH(64, Z.enc, WfT, Z.T, bf, RR, HD, 1024, 1024, 1024, HD,
          0,0,0,0,0,0, 1,1,1, z0, 1.f, 0, 0);

    add_ln_kernel<<<RR, 256>>>(Z.T, Z.e, gg, bb, Z.e, Z.enc);
}

// Decoder cross-attn layer (h=4, d=128). State: g_qb + xrq (= enc region 2).
static void cross_attn(Bufs& Z, int i, const __half* Wct, const __half* WfT,
                       const float* bf, const float* gg, const float* bb)
{
    const float scale = rsqrtf(128.f);
    Offs z0 = {};
    __half* xrq = Z.enc + 2 * ENCR;
    const int nbC = (RR * 512 + 255) / 256;

    if (i == 0) {
        Offs oV = {}; oV.b[0] = (long)512 * 512; oV.c[0] = 512;
        gemmH(64, Z.enc, Wct, Z.QKV, nullptr, RR, 512, HD, 1024, HD, QW,
              0,0,0,0,0,0, 1,1,1, oV, 1.f, 0, 1);
        skinny_cols<<<nbC, 256>>>(Z.Fdq, Z.Tq0, 512, Z.QKV, 1024);
    } else {
        Offs oVQ = {};
        oVQ.a[0] = 0;        oVQ.b[0] = (long)512 * 512;  oVQ.c[0] = 512;
        oVQ.a[1] = 2 * ENCR; oVQ.b[1] = (long)1024 * 512; oVQ.c[1] = 1024;
        gemmH(64, Z.enc, Wct, Z.QKV, nullptr, RR, 512, HD, 1024, HD, QW,
              0,0,0,0,0,0, 1,1,2, oVQ, 1.f, 0, 1);
    }
    skinny_cols<<<nbC, 256>>>(Z.Fdk, Z.Tdk + (long)i * 4 * 512, 512, Z.QKV, 0);

    transpose_v<<<dim3(32, 4, 16), dim3(32, 8)>>>(Z.QKV, Z.Vt, QW, 128, 4, 1024, 0);

    Offs oQK = {}; oQK.a[0] = 1024;
    gemmH(128, Z.QKV, Z.QKV, Z.S, nullptr, 1024, 1024, 128, QW, QW, 1024,
          (long)1024 * QW, 128, (long)1024 * QW, 128,
          (long)4 * 1024 * 1024, (long)1024 * 1024,
          4, 4, 1, oQK, scale, 0, 0);

    softmax1<<<16 * 1024, 256>>>(Z.S, Z.S16);

    gemmH(64, Z.S16, Z.Vt, xrq + 512, nullptr, 1024, 128, 1024, 1024, 1024, 1024,
          (long)4 * 1024 * 1024, (long)1024 * 1024,
          (long)4 * 128 * 1024, (long)128 * 1024,
          (long)1024 * 1024, 128,
          4, 4, 1, z0, 1.f, 0, 1);

    gemmH(64, xrq, WfT, Z.T, bf, RR, HD, 1024, 1024, 1024, HD,
          0,0,0,0,0,0, 1,1,1, z0, 1.f, 0, 0);

    add_ln_kernel<<<RR, 256>>>(Z.T, Z.qb, gg, bb, Z.qb, xrq);
}

extern "C" void kernel_launch(void* const* d_in, const int* in_sizes, int n_in,
                              void* d_out, int out_size)
{
    const float* context_x = (const float*)d_in[0];
    const float* context_y = (const float*)d_in[1];
    const float* target_x  = (const float*)d_in[2];
    const float* in_W = (const float*)d_in[3];
    const float* in_b = (const float*)d_in[4];
    const float* cx_W = (const float*)d_in[5];
    const float* cx_b = (const float*)d_in[6];
    const float* tx_W = (const float*)d_in[7];
    const float* tx_b = (const float*)d_in[8];
    const float* sc_Wk = (const float*)d_in[9];
    const float* sc_Wv = (const float*)d_in[10];
    const float* sc_Wq = (const float*)d_in[11];
    const float* sc_Wf = (const float*)d_in[12];
    const float* sc_bf = (const float*)d_in[13];
    const float* sc_g  = (const float*)d_in[14];
    const float* sc_b  = (const float*)d_in[15];
    const float* ca_Wk = (const float*)d_in[16];
    const float* ca_Wv = (const float*)d_in[17];
    const float* ca_Wq = (const float*)d_in[18];
    const float* ca_Wf = (const float*)d_in[19];
    const float* ca_bf = (const float*)d_in[20];
    const float* ca_g  = (const float*)d_in[21];
    const float* ca_b  = (const float*)d_in[22];

    Bufs Z;
    cudaGetSymbolAddress((void**)&Z.e,    g_e);
    cudaGetSymbolAddress((void**)&Z.qb,   g_qb);
    cudaGetSymbolAddress((void**)&Z.T,    g_T);
    cudaGetSymbolAddress((void**)&Z.S,    g_S);
    cudaGetSymbolAddress((void**)&Z.enc,  g_enc);
    cudaGetSymbolAddress((void**)&Z.QKV,  g_QKV);
    cudaGetSymbolAddress((void**)&Z.Vt,   g_Vt);
    cudaGetSymbolAddress((void**)&Z.S16,  g_S16);
    cudaGetSymbolAddress((void**)&Z.Wc,   g_Wc);
    cudaGetSymbolAddress((void**)&Z.Wf,   g_Wf);
    cudaGetSymbolAddress((void**)&Z.F,    g_F);
    cudaGetSymbolAddress((void**)&Z.Fdk,  g_Fdk);
    cudaGetSymbolAddress((void**)&Z.Fdq,  g_Fdq);
    cudaGetSymbolAddress((void**)&Z.Tenc, g_Tenc);
    cudaGetSymbolAddress((void**)&Z.Tdk,  g_Tdk);
    cudaGetSymbolAddress((void**)&Z.Tq0,  g_Tq0);

    const long WCL = (long)QW * 512;     // fused QKV weight per layer (halfs)
    const long WFL = (long)512 * 1024;   // Wf per layer (halfs)

    // ---- prep ----
    wprep_qkv<<<dim3(16, 16, 12), dim3(32, 8)>>>(sc_Wk, sc_Wv, sc_Wq,
                                                 ca_Wk, ca_Wv, ca_Wq, Z.Wc);
    wprep_wf<<<dim3(32, 16, 4), dim3(32, 8)>>>(sc_Wf, ca_Wf, Z.Wf);
    build_F<<<(RR + 255) / 256, 256>>>(context_x, context_y, target_x,
                                       Z.F, Z.Fdk, Z.Fdq);
    tproj_enc<<<(2 * 4 * QW * 32 + 255) / 256, 256>>>(sc_Wk, sc_Wv, sc_Wq, in_W, in_b, Z.Tenc);
    tproj_dec<<<(3 * 4 * 512 * 32 + 255) / 256, 256>>>(ca_Wk, ca_Wq, cx_W, cx_b,
                                                       tx_W, tx_b, Z.Tdk, Z.Tq0);

    const int nthr = 256, nblk = (RR * HD + nthr - 1) / nthr;

    // encoder state e (fp32 exact + fp16 region0)
    proj_in_kernel<<<nblk, nthr>>>(context_x, context_y, in_W, in_b, Z.e, Z.enc, 1024, 0);

    // ---- encoder: 2 self layers (layer 1 via skinny QKV), then 3x2 cross ----
    sc_attn(Z, 0, Z.F, Z.Tenc, Z.Wc, Z.Wf,
            sc_bf, sc_g, sc_b);
    sc_attn(Z, 1, nullptr, nullptr, Z.Wc + WCL, Z.Wf + WFL,
            sc_bf + HD, sc_g + HD, sc_b + HD);

    for (int s = 1; s <= 3; s++)
        for (int i = 0; i < 2; i++)
            sc_attn(Z, 2, Z.F + (long)s * RR * 4, Z.Tenc + (long)i * 4 * QW,
                    Z.Wc + i * WCL, Z.Wf + i * WFL,
                    sc_bf + i * HD, sc_g + i * HD, sc_b + i * HD);

    // ---- decoder ----
    proj1_kernel<<<nblk, nthr>>>(target_x, tx_W, tx_b, Z.qb, Z.enc + 2 * ENCR, 1024);

    for (int i = 0; i < 2; i++)
        cross_attn(Z, i, Z.Wc + (2 + i) * WCL, Z.Wf + (2 + i) * WFL,
                   ca_bf + i * HD, ca_g + i * HD, ca_b + i * HD);

    cudaMemcpyAsync(d_out, Z.qb, (size_t)RR * HD * sizeof(float),
                    cudaMemcpyDeviceToDevice);
}

// round 17
// speedup vs baseline: 1.5401x; 1.5401x over previous
#include <cuda_runtime.h>
#include <cuda_fp16.h>
#include <math.h>
#include <stdint.h>

// ---------------------------------------------------------------------------
// MultidomainEncoder: B=4, N=M=1024, H=512.
// Round 16: revert to R10 configuration (TN=128 GEMM everywhere);
// replace tproj prep kernels with coalesced block-per-column-tile versions.
// ---------------------------------------------------------------------------

#define RR   4096          // B*N == B*M rows
#define HD   512           // model dim
#define QW   1536          // fused QKV row width

__device__ float  g_e   [RR * HD];                    // exact encoder state
__device__ __half g_enc [3 * (size_t)RR * 1024];      // region0: [x|R]; region2: decoder [q|R]
__device__ float  g_qb  [RR * HD];                    // exact decoder state
__device__ float  g_T   [RR * HD];
__device__ __half g_QKV [2 * (size_t)RR * QW];        // QKV buffers (state / x2)
__device__ __half g_Vt  [(size_t)8 * 1024 * 1024];    // transposed V
__device__ float  g_S   [(size_t)32 * 1024 * 1024];   // pre-softmax scores (fp32)
__device__ __half g_S16 [(size_t)8 * 1024 * 2048];    // folded probs (fp16)
__device__ __half g_Wc  [4 * (size_t)QW * 512];       // transposed fused QKV weights
__device__ __half g_Wf  [4 * (size_t)512 * 1024];     // transposed full Wf per layer
__device__ float  g_F   [4 * (size_t)RR * 4];         // encoder rank-4 factors per stream
__device__ float  g_Fdk [RR * 4];                     // decoder K factor [cx,1,0,0]
__device__ float  g_Fdq [RR * 4];                     // decoder Q factor [tx,1,0,0]
__device__ float  g_Tenc[2 * 4 * QW];                 // M_aug @ Wqkv_i  (fp32)
__device__ float  g_Tdk [2 * 4 * 512];                // Mcx @ Wk_ca_i
__device__ float  g_Tq0 [4 * 512];                    // Mtx @ Wq_ca_0

static const long QBUF  = (long)RR * QW;              // QKV buffer stride (halfs)
static const long SSEGf = (long)8 * 1024 * 1024;      // S segment per combo (floats)
static const long ENCR  = (long)RR * 1024;            // one g_enc region (halfs)

// ---------------------------------------------------------------------------
// helpers
// ---------------------------------------------------------------------------
__device__ __forceinline__ void mma_f16(float c[4], const uint32_t a[4], const uint32_t b[2]) {
    asm volatile(
        "mma.sync.aligned.m16n8k16.row.col.f32.f16.f16.f32 "
        "{%0,%1,%2,%3}, {%4,%5,%6,%7}, {%8,%9}, {%0,%1,%2,%3};"
        : "+f"(c[0]), "+f"(c[1]), "+f"(c[2]), "+f"(c[3])
        : "r"(a[0]), "r"(a[1]), "r"(a[2]), "r"(a[3]), "r"(b[0]), "r"(b[1]));
}

__device__ __forceinline__ void cp16(uint32_t* dst, const void* src) {
    uint32_t d = (uint32_t)__cvta_generic_to_shared(dst);
    asm volatile("cp.async.cg.shared.global [%0], [%1], 16;" :: "r"(d), "l"(src));
}
#define CP_COMMIT() asm volatile("cp.async.commit_group;" ::: "memory")
#define CP_WAIT1()  asm volatile("cp.async.wait_group 1;"  ::: "memory")
#define CP_WAIT0()  asm volatile("cp.async.wait_group 0;"  ::: "memory")

struct Offs { long a[4]; long b[4]; long c[4]; };

// ---------------------------------------------------------------------------
// fp16 GEMM:  C[m,n] = alpha * sum_k A[m,k] * B[n,k]  [+bias] [+C]
// A: [M,K] row-major fp16 (lda); B: [N,K] row-major fp16 (ldb).
// C: fp32 (outHalf=0) or fp16 (outHalf=1).
// Tile 128x128x32, 256 threads (8 warps, warp tile 64x32), cp.async 2-stage.
// ---------------------------------------------------------------------------
#define WPR 20   // words per smem row (16 data + 4 pad)

__global__ void __launch_bounds__(256)
gemm_h(const __half* __restrict__ A, const __half* __restrict__ B,
       void* __restrict__ Cv, const float* __restrict__ bias,
       int K, int lda, int ldb, int ldc,
       long sAb, long sAh, long sBb, long sBh, long sCb, long sCh,
       int nh, int nzc, Offs off, float alpha, int accumulate, int outHalf)
{
    __shared__ uint32_t sA[2][128 * WPR];
    __shared__ uint32_t sB[2][128 * WPR];

    int z   = blockIdx.z;
    int cmb = z / nzc;
    int inn = z - cmb * nzc;
    int bb  = inn / nh;
    int hh  = inn - bb * nh;
    A += off.a[cmb] + (long)bb * sAb + (long)hh * sAh;
    B += off.b[cmb] + (long)bb * sBb + (long)hh * sBh;
    long coff = off.c[cmb] + (long)bb * sCb + (long)hh * sCh;

    const int row0 = blockIdx.y * 128;
    const int col0 = blockIdx.x * 128;
    const int tid  = threadIdx.x;
    const int wid  = tid >> 5;
    const int lane = tid & 31;
    const int wM0 = (wid & 1) * 64;
    const int wN0 = (wid >> 1) * 32;
    const int gid = lane >> 2;
    const int tig = lane & 3;

    float acc[4][4][4] = {};

    const int lrow = tid >> 1;
    const int lsel = tid & 1;

    auto loadTile = [&](int t, int s) {
        const __half* ga = A + (long)(row0 + lrow) * lda + t * 32 + lsel * 16;
        const __half* gb = B + (long)(col0 + lrow) * ldb + t * 32 + lsel * 16;
        uint32_t* sa = &sA[s][lrow * WPR + lsel * 8];
        uint32_t* sb = &sB[s][lrow * WPR + lsel * 8];
        cp16(sa, ga); cp16(sa + 4, ga + 8);
        cp16(sb, gb); cp16(sb + 4, gb + 8);
    };

    const int nT = K / 32;
    loadTile(0, 0);
    CP_COMMIT();

    for (int t = 0; t < nT; t++) {
        int s = t & 1;
        if (t + 1 < nT) {
            loadTile(t + 1, s ^ 1);
            CP_COMMIT();
            CP_WAIT1();
        } else {
            CP_WAIT0();
        }
        __syncthreads();

        const uint32_t* Ap = sA[s];
        const uint32_t* Bp = sB[s];
#pragma unroll
        for (int ko = 0; ko < 16; ko += 8) {
            uint32_t af[4][4], bfr[4][2];
#pragma unroll
            for (int mt = 0; mt < 4; mt++) {
                int m = wM0 + mt * 16 + gid;
                af[mt][0] = Ap[m * WPR + ko + tig];
                af[mt][1] = Ap[(m + 8) * WPR + ko + tig];
                af[mt][2] = Ap[m * WPR + ko + 4 + tig];
                af[mt][3] = Ap[(m + 8) * WPR + ko + 4 + tig];
            }
#pragma unroll
            for (int nt = 0; nt < 4; nt++) {
                int n = wN0 + nt * 8 + gid;
                bfr[nt][0] = Bp[n * WPR + ko + tig];
                bfr[nt][1] = Bp[n * WPR + ko + 4 + tig];
            }
#pragma unroll
            for (int mt = 0; mt < 4; mt++)
#pragma unroll
                for (int nt = 0; nt < 4; nt++)
                    mma_f16(acc[mt][nt], af[mt], bfr[nt]);
        }
        __syncthreads();
    }

    if (!outHalf) {
        float* C = (float*)Cv + coff;
#pragma unroll
        for (int mt = 0; mt < 4; mt++) {
            int r = row0 + wM0 + mt * 16 + gid;
#pragma unroll
            for (int nt = 0; nt < 4; nt++) {
                int c = col0 + wN0 + nt * 8 + tig * 2;
                float b0 = 0.f, b1 = 0.f;
                if (bias) { b0 = bias[c]; b1 = bias[c + 1]; }
                float2 v0, v1;
                v0.x = alpha * acc[mt][nt][0] + b0;
                v0.y = alpha * acc[mt][nt][1] + b1;
                v1.x = alpha * acc[mt][nt][2] + b0;
                v1.y = alpha * acc[mt][nt][3] + b1;
                float* p0 = &C[(long)r * ldc + c];
                float* p1 = &C[(long)(r + 8) * ldc + c];
                if (accumulate) {
                    float2 o0 = *(const float2*)p0, o1 = *(const float2*)p1;
                    v0.x += o0.x; v0.y += o0.y; v1.x += o1.x; v1.y += o1.y;
                }
                *(float2*)p0 = v0;
                *(float2*)p1 = v1;
            }
        }
    } else {
        __half* C = (__half*)Cv + coff;
#pragma unroll
        for (int mt = 0; mt < 4; mt++) {
            int r = row0 + wM0 + mt * 16 + gid;
#pragma unroll
            for (int nt = 0; nt < 4; nt++) {
                int c = col0 + wN0 + nt * 8 + tig * 2;
                __half2 h0 = __floats2half2_rn(alpha * acc[mt][nt][0], alpha * acc[mt][nt][1]);
                __half2 h1 = __floats2half2_rn(alpha * acc[mt][nt][2], alpha * acc[mt][nt][3]);
                *(__half2*)&C[(long)r * ldc + c]       = h0;
                *(__half2*)&C[(long)(r + 8) * ldc + c] = h1;
            }
        }
    }
}

// ---------------------------------------------------------------------------
// Single softmax (L=1024): S fp32 in, S16 fp16 out.
// ---------------------------------------------------------------------------
__global__ void softmax1(const float* __restrict__ S, __half* __restrict__ S16)
{
    const float4* p = (const float4*)(S + (long)blockIdx.x * 1024);
    __half2* o = (__half2*)(S16 + (long)blockIdx.x * 1024);
    int tid = threadIdx.x, lane = tid & 31, wid = tid >> 5;
    __shared__ float red[16];

    float4 v = p[tid];
    float m = fmaxf(fmaxf(v.x, v.y), fmaxf(v.z, v.w));
#pragma unroll
    for (int t = 16; t > 0; t >>= 1) m = fmaxf(m, __shfl_xor_sync(0xffffffffu, m, t));
    if (lane == 0) red[wid] = m;
    __syncthreads();
    m = red[0];
#pragma unroll
    for (int i = 1; i < 8; i++) m = fmaxf(m, red[i]);

    v.x = __expf(v.x - m); v.y = __expf(v.y - m);
    v.z = __expf(v.z - m); v.w = __expf(v.w - m);
    float sum = v.x + v.y + v.z + v.w;
#pragma unroll
    for (int t = 16; t > 0; t >>= 1) sum += __shfl_xor_sync(0xffffffffu, sum, t);
    if (lane == 0) red[8 + wid] = sum;
    __syncthreads();
    sum = red[8];
#pragma unroll
    for (int i = 1; i < 8; i++) sum += red[8 + i];
    float inv = 1.f / sum;

    o[2 * tid]     = __floats2half2_rn(v.x * inv, v.y * inv);
    o[2 * tid + 1] = __floats2half2_rn(v.z * inv, v.w * inv);
}

// ---------------------------------------------------------------------------
// Paired softmax + fold (cross layers): g=0 -> segs {0,2}, g=1 -> segs {1,3}.
// ---------------------------------------------------------------------------
__global__ void softmax_pair(const float* __restrict__ S, __half* __restrict__ S16)
{
    int bid = blockIdx.x;
    int g   = bid >> 13;
    int rem = bid & 8191;
    long roff = (long)rem << 10;
    const float4* pa = (const float4*)(S + (long)g * SSEGf + roff);
    const float4* pb = (const float4*)(S + (long)(g + 2) * SSEGf + roff);
    __half2* out = (__half2*)(S16 + ((long)rem << 11) + ((long)g << 10));
    int tid = threadIdx.x, lane = tid & 31, wid = tid >> 5;
    __shared__ float red[32];

    float4 va = pa[tid], vb = pb[tid];
    float ma = fmaxf(fmaxf(va.x, va.y), fmaxf(va.z, va.w));
    float mb = fmaxf(fmaxf(vb.x, vb.y), fmaxf(vb.z, vb.w));
#pragma unroll
    for (int t = 16; t > 0; t >>= 1) {
        ma = fmaxf(ma, __shfl_xor_sync(0xffffffffu, ma, t));
        mb = fmaxf(mb, __shfl_xor_sync(0xffffffffu, mb, t));
    }
    if (lane == 0) { red[wid] = ma; red[8 + wid] = mb; }
    __syncthreads();
    ma = red[0]; mb = red[8];
#pragma unroll
    for (int i = 1; i < 8; i++) { ma = fmaxf(ma, red[i]); mb = fmaxf(mb, red[8 + i]); }

    va.x = __expf(va.x - ma); va.y = __expf(va.y - ma);
    va.z = __expf(va.z - ma); va.w = __expf(va.w - ma);
    vb.x = __expf(vb.x - mb); vb.y = __expf(vb.y - mb);
    vb.z = __expf(vb.z - mb); vb.w = __expf(vb.w - mb);
    float sa = va.x + va.y + va.z + va.w;
    float sb = vb.x + vb.y + vb.z + vb.w;
#pragma unroll
    for (int t = 16; t > 0; t >>= 1) {
        sa += __shfl_xor_sync(0xffffffffu, sa, t);
        sb += __shfl_xor_sync(0xffffffffu, sb, t);
    }
    if (lane == 0) { red[16 + wid] = sa; red[24 + wid] = sb; }
    __syncthreads();
    sa = red[16]; sb = red[24];
#pragma unroll
    for (int i = 1; i < 8; i++) { sa += red[16 + i]; sb += red[24 + i]; }
    float ia = 1.f / sa, ib = 1.f / sb;

    out[2 * tid]     = __floats2half2_rn(va.x * ia + vb.x * ib, va.y * ia + vb.y * ib);
    out[2 * tid + 1] = __floats2half2_rn(va.z * ia + vb.z * ib, va.w * ia + vb.w * ib);
}

// ---------------------------------------------------------------------------
// transpose V head-slices: src [4*1024 rows, ldsrc] cols [512 + h*d, +d)
//  -> dst[z][d][dstLd] at column offset dstOff  (z = b*hn + h)
// ---------------------------------------------------------------------------
__global__ void transpose_v(const __half* __restrict__ src, __half* __restrict__ dst,
                            int ldsrc, int d, int hn, int dstLd, int dstOff)
{
    __shared__ __half t[32][34];
    int z = blockIdx.z;
    int b = z / hn, h = z - b * hn;
    int m0 = blockIdx.x * 32, c0 = blockIdx.y * 32;
    const __half* s = src + (long)(b * 1024) * ldsrc + 512 + h * d;
    int tx = threadIdx.x, ty = threadIdx.y;
#pragma unroll
    for (int i = 0; i < 4; i++)
        t[ty + i * 8][tx] = s[(long)(m0 + ty + i * 8) * ldsrc + c0 + tx];
    __syncthreads();
    __half* o = dst + (long)z * d * dstLd + dstOff;
#pragma unroll
    for (int i = 0; i < 4; i++)
        o[(long)(c0 + ty + i * 8) * dstLd + m0 + tx] = t[tx][ty + i * 8];
}

// ---------------------------------------------------------------------------
// out = LayerNorm(tmp + res) * g + b ; fp32 exact + fp16 state (ld 1024)
// ---------------------------------------------------------------------------
__global__ void add_ln_kernel(const float* __restrict__ tmp, const float* __restrict__ res,
                              const float* __restrict__ g, const float* __restrict__ b,
                              float* __restrict__ out, __half* __restrict__ outh)
{
    long row = blockIdx.x;
    const float* t = tmp + row * (long)HD;
    const float* r = res + row * (long)HD;
    float* o = out + row * (long)HD;
    __half* oh = outh + row * 1024;
    __shared__ float red[256];
    int tid = threadIdx.x;

    float v0 = t[tid]       + r[tid];
    float v1 = t[tid + 256] + r[tid + 256];
    red[tid] = v0 + v1; __syncthreads();
    for (int s = 128; s > 0; s >>= 1) { if (tid < s) red[tid] += red[tid + s]; __syncthreads(); }
    float mean = red[0] * (1.f / HD);
    __syncthreads();
    float d0 = v0 - mean, d1 = v1 - mean;
    red[tid] = d0 * d0 + d1 * d1; __syncthreads();
    for (int s = 128; s > 0; s >>= 1) { if (tid < s) red[tid] += red[tid + s]; __syncthreads(); }
    float rstd = rsqrtf(red[0] * (1.f / HD) + 1e-5f);
    float w0 = d0 * rstd * g[tid]       + b[tid];
    float w1 = d1 * rstd * g[tid + 256] + b[tid + 256];
    o[tid]       = w0;
    o[tid + 256] = w1;
    oh[tid]       = __float2half_rn(w0);
    oh[tid + 256] = __float2half_rn(w1);
}

// ---------------------------------------------------------------------------
// Input projections
// ---------------------------------------------------------------------------
__global__ void proj_in_kernel(const float* __restrict__ cx, const float* __restrict__ cy,
                               const float* __restrict__ W, const float* __restrict__ bias,
                               float* __restrict__ out, __half* __restrict__ outh,
                               int ldo, int j)
{
    int idx = blockIdx.x * blockDim.x + threadIdx.x;
    if (idx >= RR * HD) return;
    int r = idx >> 9;
    int h = idx & (HD - 1);
    float x0 = cx[r];
    float y0 = cy[r * 8 + j * 2];
    float y1 = cy[r * 8 + j * 2 + 1];
    float v = x0 * W[h] + y0 * W[HD + h] + y1 * W[2 * HD + h] + bias[h];
    if (out) out[idx] = v;
    outh[(long)r * ldo + h] = __float2half_rn(v);
}

__global__ void proj1_kernel(const float* __restrict__ x, const float* __restrict__ W,
                             const float* __restrict__ bias,
                             float* __restrict__ out, __half* __restrict__ outh, int ldo)
{
    int idx = blockIdx.x * blockDim.x + threadIdx.x;
    if (idx >= RR * HD) return;
    int r = idx >> 9;
    int h = idx & (HD - 1);
    float v = x[r] * W[h] + bias[h];
    if (out) out[idx] = v;
    outh[(long)r * ldo + h] = __float2half_rn(v);
}

// ---------------------------------------------------------------------------
// Rank-4 machinery
// ---------------------------------------------------------------------------
__global__ void build_F(const float* __restrict__ cx, const float* __restrict__ cy,
                        const float* __restrict__ tx,
                        float* __restrict__ F, float* __restrict__ Fdk,
                        float* __restrict__ Fdq)
{
    int r = blockIdx.x * blockDim.x + threadIdx.x;
    if (r >= RR) return;
    float c = cx[r];
#pragma unroll
    for (int s = 0; s < 4; s++) {
        float4 v = make_float4(c, cy[r * 8 + s * 2], cy[r * 8 + s * 2 + 1], 1.f);
        *(float4*)&F[((long)s * RR + r) * 4] = v;
    }
    *(float4*)&Fdk[r * 4] = make_float4(c, 1.f, 0.f, 0.f);
    *(float4*)&Fdq[r * 4] = make_float4(tx[r], 1.f, 0.f, 0.f);
}

// Coalesced tproj_enc: grid (6 col-tiles, 2 layers), 256 threads.
// Tenc[i][k4][c] = sum_k M_aug[k4][k] * W_{i,sel(c)}[k][c%512].
// Inner loop reads W[k][n0 + tid] coalesced across the block; m in smem.
__global__ void tproj_enc(const float* __restrict__ Wk, const float* __restrict__ Wv,
                          const float* __restrict__ Wq, const float* __restrict__ inW,
                          const float* __restrict__ inb, float* __restrict__ T)
{
    __shared__ float sm[4 * 512];
    int tid = threadIdx.x;
    int i = blockIdx.y;
    int c0 = blockIdx.x * 256;

    // load M_aug rows (inW is [3][512] row-major; row 3 = inb)
#pragma unroll
    for (int j = 0; j < 8; j++) {
        int k = tid + j * 256;                 // 0..2047
        int k4 = k >> 9, kk = k & 511;
        sm[k] = (k4 < 3) ? inW[k4 * 512 + kk] : inb[kk];
    }
    __syncthreads();

    int c = c0 + tid;                          // 0..1535
    const float* W = (c < 512 ? Wk : c < 1024 ? Wv : Wq) + (long)i * 512 * 512;
    int n = c & 511;

    float a0 = 0.f, a1 = 0.f, a2 = 0.f, a3 = 0.f;
#pragma unroll 4
    for (int k = 0; k < 512; k++) {
        float w = W[(long)k * 512 + n];        // coalesced across block
        a0 += sm[k] * w;
        a1 += sm[512 + k] * w;
        a2 += sm[1024 + k] * w;
        a3 += sm[1536 + k] * w;
    }
    float* Ti = T + (long)i * 4 * QW;
    Ti[c] = a0; Ti[QW + c] = a1; Ti[2 * QW + c] = a2; Ti[3 * QW + c] = a3;
}

// Coalesced tproj_dec: grid (2 col-tiles, 3 groups), 256 threads.
// grp 0,1: Tdk[grp] rows {cxW@Wk, cxb@Wk, 0, 0}; grp 2: Tq0 rows {txW@Wq0, txb@Wq0, 0, 0}.
__global__ void tproj_dec(const float* __restrict__ caWk, const float* __restrict__ caWq,
                          const float* __restrict__ cxW, const float* __restrict__ cxb,
                          const float* __restrict__ txW, const float* __restrict__ txb,
                          float* __restrict__ Tdk, float* __restrict__ Tq0)
{
    __shared__ float sm[2 * 512];
    int tid = threadIdx.x;
    int grp = blockIdx.y;
    int n = blockIdx.x * 256 + tid;            // 0..511

    const float* m0 = (grp < 2) ? cxW : txW;
    const float* m1 = (grp < 2) ? cxb : txb;
#pragma unroll
    for (int j = 0; j < 4; j++) {
        int k = tid + j * 256;                 // 0..1023
        sm[k] = (k < 512) ? m0[k] : m1[k - 512];
    }
    __syncthreads();

    const float* W = (grp < 2) ? (caWk + (long)grp * 512 * 512) : caWq;
    float a0 = 0.f, a1 = 0.f;
#pragma unroll 4
    for (int k = 0; k < 512; k++) {
        float w = W[(long)k * 512 + n];
        a0 += sm[k] * w;
        a1 += sm[512 + k] * w;
    }
    float* Td = (grp < 2) ? (Tdk + (long)grp * 2048) : Tq0;
    Td[n] = a0; Td[512 + n] = a1; Td[1024 + n] = 0.f; Td[1536 + n] = 0.f;
}

// out[r][c] (ld QW) = fp16( F[r][:] . T[:][c] ), c in [0,1536)
__global__ void skinny_full(const float* __restrict__ F, const float* __restrict__ T,
                            __half* __restrict__ out)
{
    int idx = blockIdx.x * blockDim.x + threadIdx.x;
    if (idx >= RR * QW) return;
    int r = idx / QW, c = idx - r * QW;
    float4 f = *(const float4*)&F[(long)r * 4];
    float v = f.x * T[c] + f.y * T[QW + c] + f.z * T[2 * QW + c] + f.w * T[3 * QW + c];
    out[(long)r * QW + c] = __float2half_rn(v);
}

// out[r][outOff + c] (ld QW) over c in [0,512); T rows have leading dim tld.
__global__ void skinny_cols(const float* __restrict__ F, const float* __restrict__ T,
                            int tld, __half* __restrict__ out, int outOff)
{
    int idx = blockIdx.x * blockDim.x + threadIdx.x;
    if (idx >= RR * 512) return;
    int r = idx >> 9, c = idx & 511;
    float4 f = *(const float4*)&F[(long)r * 4];
    float v = f.x * T[c] + f.y * T[tld + c] + f.z * T[2 * tld + c] + f.w * T[3 * tld + c];
    out[(long)r * QW + outOff + c] = __float2half_rn(v);
}

// Direct transposed V for x2 streams (encoder, d=256, hn=2):
// Vt[z][dd][ld=2048] at off 1024; T = Tenc_i + 512 (V block, ld QW).
__global__ void skinny_vt(const float* __restrict__ F, const float* __restrict__ T,
                          __half* __restrict__ Vt)
{
    int idx = blockIdx.x * blockDim.x + threadIdx.x;
    if (idx >= 8 * 256 * 1024) return;
    int n = idx & 1023;
    int rest = idx >> 10;
    int dd = rest & 255;
    int z = rest >> 8;
    int b = z >> 1, h = z & 1;
    long r = (long)b * 1024 + n;
    int c = h * 256 + dd;
    float4 f = *(const float4*)&F[r * 4];
    float v = f.x * T[c] + f.y * T[QW + c] + f.z * T[2 * QW + c] + f.w * T[3 * QW + c];
    Vt[(long)z * 256 * 2048 + (long)dd * 2048 + 1024 + n] = __float2half_rn(v);
}

// ---------------------------------------------------------------------------
// Weight prep (tiled transposes)
// ---------------------------------------------------------------------------
__global__ void wprep_qkv(const float* __restrict__ sWk, const float* __restrict__ sWv,
                          const float* __restrict__ sWq, const float* __restrict__ cWk,
                          const float* __restrict__ cWv, const float* __restrict__ cWq,
                          __half* __restrict__ Wc)
{
    __shared__ float t[32][33];
    int z = blockIdx.z;
    int L = z / 3, m = z - L * 3;
    const float* base;
    if (L < 2) base = (m == 0 ? sWk : m == 1 ? sWv : sWq) + (long)L * 512 * 512;
    else       base = (m == 0 ? cWk : m == 1 ? cWv : cWq) + (long)(L - 2) * 512 * 512;
    __half* dst = Wc + (long)L * QW * 512 + (long)m * 512 * 512;
    int n0 = blockIdx.x * 32, k0 = blockIdx.y * 32;
    int tx = threadIdx.x, ty = threadIdx.y;
#pragma unroll
    for (int i = 0; i < 4; i++)
        t[ty + i * 8][tx] = base[(long)(k0 + ty + i * 8) * 512 + n0 + tx];
    __syncthreads();
#pragma unroll
    for (int i = 0; i < 4; i++)
        dst[(long)(n0 + ty + i * 8) * 512 + k0 + tx] = __float2half_rn(t[tx][ty + i * 8]);
}

__global__ void wprep_wf(const float* __restrict__ sWf, const float* __restrict__ cWf,
                         __half* __restrict__ Wf)
{
    __shared__ float t[32][33];
    int z = blockIdx.z;
    const float* src = (z < 2 ? sWf : cWf) + (long)(z & 1) * 1024 * 512;
    __half* dst = Wf + (long)z * 512 * 1024;
    int k0 = blockIdx.x * 32, n0 = blockIdx.y * 32;
    int tx = threadIdx.x, ty = threadIdx.y;
#pragma unroll
    for (int i = 0; i < 4; i++)
        t[ty + i * 8][tx] = src[(long)(k0 + ty + i * 8) * 512 + n0 + tx];
    __syncthreads();
#pragma unroll
    for (int i = 0; i < 4; i++)
        dst[(long)(n0 + ty + i * 8) * 1024 + k0 + tx] = __float2half_rn(t[tx][ty + i * 8]);
}

// ---------------------------------------------------------------------------
// Host orchestration
// ---------------------------------------------------------------------------
static void gemmH(const __half* A, const __half* B, void* C, const float* bias,
                  int M, int N, int K, int lda, int ldb, int ldc,
                  long sAb, long sAh, long sBb, long sBh, long sCb, long sCh,
                  int nb, int nh, int ncomb, const Offs& off,
                  float alpha, int acc, int outHalf)
{
    dim3 grid(N / 128, M / 128, ncomb * nb * nh);
    gemm_h<<<grid, 256>>>(A, B, C, bias, K, lda, ldb, ldc,
                          sAb, sAh, sBb, sBh, sCb, sCh,
                          nh, nb * nh, off, alpha, acc, outHalf);
}

struct Bufs {
    float *e, *qb, *T, *S, *F, *Fdk, *Fdq, *Tenc, *Tdk, *Tq0;
    __half *enc, *QKV, *Vt, *S16, *Wc, *Wf;
};

// Encoder layer. mode: 0 = self via skinny QKV (layer 1 only),
//                      1 = self via full GEMM, 2 = cross-domain.
static void sc_attn(Bufs& Z, int mode, const float* Fs, const float* Tl,
                    const __half* Wct, const __half* WfT,
                    const float* bf, const float* gg, const float* bb)
{
    const float scale = rsqrtf(256.f);
    Offs z0 = {};
    bool same = (mode != 2);
    const int nbF = (RR * QW + 255) / 256;
    const int nbC = (RR * 512 + 255) / 256;
    const int nbV = (8 * 256 * 1024 + 255) / 256;

    // state QKV
    if (mode == 0)
        skinny_full<<<nbF, 256>>>(Fs, Tl, Z.QKV);
    else
        gemmH(Z.enc, Wct, Z.QKV, nullptr, RR, QW, HD, 1024, HD, QW,
              0,0,0,0,0,0, 1,1,1, z0, 1.f, 0, 1);

    if (mode == 2) {
        skinny_cols<<<nbC, 256>>>(Fs, Tl,        QW, Z.QKV + QBUF, 0);
        skinny_cols<<<nbC, 256>>>(Fs, Tl + 1024, QW, Z.QKV + QBUF, 1024);
        skinny_vt<<<nbV, 256>>>(Fs, Tl + 512, Z.Vt);
        transpose_v<<<dim3(32, 8, 8), dim3(32, 8)>>>(Z.QKV, Z.Vt, QW, 256, 2, 2048, 0);
    } else {
        transpose_v<<<dim3(32, 8, 8), dim3(32, 8)>>>(Z.QKV, Z.Vt, QW, 256, 2, 1024, 0);
    }

    // QK scores -> S (fp32)
    {
        Offs oQK = {};
        int nc = 1;
        if (same) {
            oQK.a[0] = 1024;
        } else {
            const long selQ[4] = {0, 1, 1, 0};
            const long selK[4] = {0, 1, 0, 1};
            for (int c = 0; c < 4; c++) {
                oQK.a[c] = selQ[c] * QBUF + 1024;
                oQK.b[c] = selK[c] * QBUF;
                oQK.c[c] = c * SSEGf;
            }
            nc = 4;
        }
        gemmH(Z.QKV, Z.QKV, Z.S, nullptr, 1024, 1024, 256, QW, QW, 1024,
              (long)1024 * QW, 256, (long)1024 * QW, 256,
              (long)2 * 1024 * 1024, (long)1024 * 1024,
              4, 2, nc, oQK, scale, 0, 0);
    }

    if (same) {
        softmax1<<<8 * 1024, 256>>>(Z.S, Z.S16);
        gemmH(Z.S16, Z.Vt, Z.enc + 512, nullptr, 1024, 256, 1024, 1024, 1024, 1024,
              (long)2 * 1024 * 1024, (long)1024 * 1024,
              (long)2 * 256 * 1024, (long)256 * 1024,
              (long)1024 * 1024, 256,
              4, 2, 1, z0, 4.f, 0, 1);
    } else {
        softmax_pair<<<2 * 8 * 1024, 256>>>(Z.S, Z.S16);
        gemmH(Z.S16, Z.Vt, Z.enc + 512, nullptr, 1024, 256, 2048, 2048, 2048, 1024,
              (long)2 * 1024 * 2048, (long)1024 * 2048,
              (long)2 * 256 * 2048, (long)256 * 2048,
              (long)1024 * 1024, 256,
              4, 2, 1, z0, 1.f, 0, 1);
    }

    gemmH(Z.enc, WfT, Z.T, bf, RR, HD, 1024, 1024, 1024, HD,
          0,0,0,0,0,0, 1,1,1, z0, 1.f, 0, 0);

    add_ln_kernel<<<RR, 256>>>(Z.T, Z.e, gg, bb, Z.e, Z.enc);
}

// Decoder cross-attn layer (h=4, d=128). State: g_qb + xrq (= enc region 2).
static void cross_attn(Bufs& Z, int i, const __half* Wct, const __half* WfT,
                       const float* bf, const float* gg, const float* bb)
{
    const float scale = rsqrtf(128.f);
    Offs z0 = {};
    __half* xrq = Z.enc + 2 * ENCR;
    const int nbC = (RR * 512 + 255) / 256;

    if (i == 0) {
        Offs oV = {}; oV.b[0] = (long)512 * 512; oV.c[0] = 512;
        gemmH(Z.enc, Wct, Z.QKV, nullptr, RR, 512, HD, 1024, HD, QW,
              0,0,0,0,0,0, 1,1,1, oV, 1.f, 0, 1);
        skinny_cols<<<nbC, 256>>>(Z.Fdq, Z.Tq0, 512, Z.QKV, 1024);
    } else {
        Offs oVQ = {};
        oVQ.a[0] = 0;        oVQ.b[0] = (long)512 * 512;  oVQ.c[0] = 512;
        oVQ.a[1] = 2 * ENCR; oVQ.b[1] = (long)1024 * 512; oVQ.c[1] = 1024;
        gemmH(Z.enc, Wct, Z.QKV, nullptr, RR, 512, HD, 1024, HD, QW,
              0,0,0,0,0,0, 1,1,2, oVQ, 1.f, 0, 1);
    }
    skinny_cols<<<nbC, 256>>>(Z.Fdk, Z.Tdk + (long)i * 4 * 512, 512, Z.QKV, 0);

    transpose_v<<<dim3(32, 4, 16), dim3(32, 8)>>>(Z.QKV, Z.Vt, QW, 128, 4, 1024, 0);

    Offs oQK = {}; oQK.a[0] = 1024;
    gemmH(Z.QKV, Z.QKV, Z.S, nullptr, 1024, 1024, 128, QW, QW, 1024,
          (long)1024 * QW, 128, (long)1024 * QW, 128,
          (long)4 * 1024 * 1024, (long)1024 * 1024,
          4, 4, 1, oQK, scale, 0, 0);

    softmax1<<<16 * 1024, 256>>>(Z.S, Z.S16);

    gemmH(Z.S16, Z.Vt, xrq + 512, nullptr, 1024, 128, 1024, 1024, 1024, 1024,
          (long)4 * 1024 * 1024, (long)1024 * 1024,
          (long)4 * 128 * 1024, (long)128 * 1024,
          (long)1024 * 1024, 128,
          4, 4, 1, z0, 1.f, 0, 1);

    gemmH(xrq, WfT, Z.T, bf, RR, HD, 1024, 1024, 1024, HD,
          0,0,0,0,0,0, 1,1,1, z0, 1.f, 0, 0);

    add_ln_kernel<<<RR, 256>>>(Z.T, Z.qb, gg, bb, Z.qb, xrq);
}

extern "C" void kernel_launch(void* const* d_in, const int* in_sizes, int n_in,
                              void* d_out, int out_size)
{
    const float* context_x = (const float*)d_in[0];
    const float* context_y = (const float*)d_in[1];
    const float* target_x  = (const float*)d_in[2];
    const float* in_W = (const float*)d_in[3];
    const float* in_b = (const float*)d_in[4];
    const float* cx_W = (const float*)d_in[5];
    const float* cx_b = (const float*)d_in[6];
    const float* tx_W = (const float*)d_in[7];
    const float* tx_b = (const float*)d_in[8];
    const float* sc_Wk = (const float*)d_in[9];
    const float* sc_Wv = (const float*)d_in[10];
    const float* sc_Wq = (const float*)d_in[11];
    const float* sc_Wf = (const float*)d_in[12];
    const float* sc_bf = (const float*)d_in[13];
    const float* sc_g  = (const float*)d_in[14];
    const float* sc_b  = (const float*)d_in[15];
    const float* ca_Wk = (const float*)d_in[16];
    const float* ca_Wv = (const float*)d_in[17];
    const float* ca_Wq = (const float*)d_in[18];
    const float* ca_Wf = (const float*)d_in[19];
    const float* ca_bf = (const float*)d_in[20];
    const float* ca_g  = (const float*)d_in[21];
    const float* ca_b  = (const float*)d_in[22];

    Bufs Z;
    cudaGetSymbolAddress((void**)&Z.e,    g_e);
    cudaGetSymbolAddress((void**)&Z.qb,   g_qb);
    cudaGetSymbolAddress((void**)&Z.T,    g_T);
    cudaGetSymbolAddress((void**)&Z.S,    g_S);
    cudaGetSymbolAddress((void**)&Z.enc,  g_enc);
    cudaGetSymbolAddress((void**)&Z.QKV,  g_QKV);
    cudaGetSymbolAddress((void**)&Z.Vt,   g_Vt);
    cudaGetSymbolAddress((void**)&Z.S16,  g_S16);
    cudaGetSymbolAddress((void**)&Z.Wc,   g_Wc);
    cudaGetSymbolAddress((void**)&Z.Wf,   g_Wf);
    cudaGetSymbolAddress((void**)&Z.F,    g_F);
    cudaGetSymbolAddress((void**)&Z.Fdk,  g_Fdk);
    cudaGetSymbolAddress((void**)&Z.Fdq,  g_Fdq);
    cudaGetSymbolAddress((void**)&Z.Tenc, g_Tenc);
    cudaGetSymbolAddress((void**)&Z.Tdk,  g_Tdk);
    cudaGetSymbolAddress((void**)&Z.Tq0,  g_Tq0);

    const long WCL = (long)QW * 512;     // fused QKV weight per layer (halfs)
    const long WFL = (long)512 * 1024;   // Wf per layer (halfs)

    // ---- prep ----
    wprep_qkv<<<dim3(16, 16, 12), dim3(32, 8)>>>(sc_Wk, sc_Wv, sc_Wq,
                                                 ca_Wk, ca_Wv, ca_Wq, Z.Wc);
    wprep_wf<<<dim3(32, 16, 4), dim3(32, 8)>>>(sc_Wf, ca_Wf, Z.Wf);
    build_F<<<(RR + 255) / 256, 256>>>(context_x, context_y, target_x,
                                       Z.F, Z.Fdk, Z.Fdq);
    tproj_enc<<<dim3(6, 2), 256>>>(sc_Wk, sc_Wv, sc_Wq, in_W, in_b, Z.Tenc);
    tproj_dec<<<dim3(2, 3), 256>>>(ca_Wk, ca_Wq, cx_W, cx_b, tx_W, tx_b, Z.Tdk, Z.Tq0);

    const int nthr = 256, nblk = (RR * HD + nthr - 1) / nthr;

    // encoder state e (fp32 exact + fp16 region0)
    proj_in_kernel<<<nblk, nthr>>>(context_x, context_y, in_W, in_b, Z.e, Z.enc, 1024, 0);

    // ---- encoder: 2 self layers (layer 1 via skinny QKV), then 3x2 cross ----
    sc_attn(Z, 0, Z.F, Z.Tenc, Z.Wc, Z.Wf,
            sc_bf, sc_g, sc_b);
    sc_attn(Z, 1, nullptr, nullptr, Z.Wc + WCL, Z.Wf + WFL,
            sc_bf + HD, sc_g + HD, sc_b + HD);

    for (int s = 1; s <= 3; s++)
        for (int i = 0; i < 2; i++)
            sc_attn(Z, 2, Z.F + (long)s * RR * 4, Z.Tenc + (long)i * 4 * QW,
                    Z.Wc + i * WCL, Z.Wf + i * WFL,
                    sc_bf + i * HD, sc_g + i * HD, sc_b + i * HD);

    // ---- decoder ----
    proj1_kernel<<<nblk, nthr>>>(target_x, tx_W, tx_b, Z.qb, Z.enc + 2 * ENCR, 1024);

    for (int i = 0; i < 2; i++)
        cross_attn(Z, i, Z.Wc + (2 + i) * WCL, Z.Wf + (2 + i) * WFL,
                   ca_bf + i * HD, ca_g + i * HD, ca_b + i * HD);

    cudaMemcpyAsync(d_out, Z.qb, (size_t)RR * HD * sizeof(float),
                    cudaMemcpyDeviceToDevice);
}